// round 7
// baseline (speedup 1.0000x reference)
#include <cuda_runtime.h>

// ODELinear: 96 independent RK4(3/8) trajectory pairs over a 64-wide MLP field.
// Unit = (pair pi, quarter q): 32 rows (16 fwd + 16 bwd), 384 CTAs, LPT by bid.
// All FMAs are packed f32x2 with ZERO packing overhead: weights duplicated in
// smem as (w,w) float2, row-pairs naturally packed via aligned LDS of the
// transposed state. Stage state + emission entirely in registers.

#define Lg 96
#define Hh 8
#define E 64
#define EH 128
#define RS 36
#define NT 256

typedef unsigned long long ull;

struct __align__(16) Smem {
    float tmpT[E][RS];   // stage input / state, transposed [feature][row 0..31]
    float HT[EH][RS];    // hidden activations, transposed
    float2 W1d[E][EH];   // duplicated-lane weights: (w,w)
    float2 W2d[EH][E];
    float2 b1d[EH];
    float2 b2d[E];
    float Ts[Lg];
};

__device__ __forceinline__ float tanh_fast(float x) {
    // 1 - 2/(e^{2x}+1): exact at saturation, rel err ~1e-6
    float e = __expf(2.0f * x);
    return 1.0f - __fdividef(2.0f, e + 1.0f);
}

__device__ __forceinline__ ull fma2(ull a, ull b, ull c) {
    ull d;
    asm("fma.rn.f32x2 %0, %1, %2, %3;" : "=l"(d) : "l"(a), "l"(b), "l"(c));
    return d;
}
__device__ __forceinline__ void unpack2(ull v, float& lo, float& hi) {
    asm("mov.b64 {%0, %1}, %2;" : "=f"(lo), "=f"(hi) : "l"(v));
}

__global__ void __launch_bounds__(NT, 1)
ode_kernel(const float* __restrict__ x, const float* __restrict__ Tg,
           const float* __restrict__ W1g, const float* __restrict__ b1g,
           const float* __restrict__ W2g, const float* __restrict__ b2g,
           float2* __restrict__ out) {
    extern __shared__ char smraw[];
    Smem* s = (Smem*)smraw;
    const int tid = threadIdx.x;
    const int pi = blockIdx.x >> 2;  // pair index 0..95, descending work => LPT
    const int q = blockIdx.x & 3;    // 16-row quarter of each trajectory
    const int trajF = pi;
    const int trajB = 95 - pi;

    // --- weights (duplicated lanes), biases, timeslots ---
    for (int t = tid; t < E * EH; t += NT) {
        float w = W1g[t];
        ((float2*)s->W1d)[t] = make_float2(w, w);
    }
    for (int t = tid; t < EH * E; t += NT) {
        float w = W2g[t];
        ((float2*)s->W2d)[t] = make_float2(w, w);
    }
    if (tid < EH) { float w = b1g[tid]; s->b1d[tid] = make_float2(w, w); }
    if (tid < E)  { float w = b2g[tid]; s->b2d[tid] = make_float2(w, w); }
    if (tid < Lg) s->Ts[tid] = Tg[tid];

    // --- initial states into tmpT: rows 0..15 = fwd quarter, 16..31 = bwd quarter ---
    for (int t = tid; t < 32 * E; t += NT) {
        int u = t >> 6, e = t & 63;
        int traj = (u < 16) ? trajF : trajB;
        int grow = q * 16 + (u & 15);
        int b = grow >> 3, h = grow & 7;
        s->tmpT[e][u] = x[(((b * Lg + traj) * Hh + h) << 6) + e];
    }
    __syncthreads();

    const int rp = tid & 15;  // row-pair id: rows 2rp, 2rp+1
    const int r2 = rp * 2;
    const int cg = tid >> 4;  // 0..15
    const int c0 = cg * 8;    // GEMM1 column base
    const int c4 = cg * 4;    // GEMM2 column base

    // persistent register tiles [col 0..3][row 0..1] for GEMM2 cols c4.., rows r2..
    float yt[4][2], x0t[4][2], Pt[4][2], Qt[4][2];
#pragma unroll
    for (int c = 0; c < 4; ++c) {
        float2 v = *(const float2*)&s->tmpT[c4 + c][r2];
        yt[c][0] = x0t[c][0] = v.x;
        yt[c][1] = x0t[c][1] = v.y;
    }

    // emission row pointers (fixed; only j varies)
    const int myTraj = (rp < 8) ? trajF : trajB;
    float2* rpt[2];
#pragma unroll
    for (int r = 0; r < 2; ++r) {
        int grow = q * 16 + ((r2 + r) & 15);
        int b = grow >> 3, h = grow & 7;
        rpt[r] = out + (size_t)(b * Lg + myTraj) * (Lg * Hh * 64) + h * 64 + c4;
    }

    // diagonal emission j == trajF (fwd rows only; trajB's diagonal comes from pair 95-pi)
    if (rp < 8) {
#pragma unroll
        for (int r = 0; r < 2; ++r) {
            float4* p = (float4*)(rpt[r] + (size_t)trajF * (Hh * 64));
            p[0] = make_float4(x0t[0][r], x0t[0][r], x0t[1][r], x0t[1][r]);
            p[1] = make_float4(x0t[2][r], x0t[2][r], x0t[3][r], x0t[3][r]);
        }
    }

    int jcur = (rp < 8) ? (pi + 1) : (94 - pi);
    const int jd = (rp < 8) ? 1 : -1;

    const int len = 95 - pi;  // identical for both batched trajectories
    for (int n = 0; n < len; ++n) {
        const float dt_f = s->Ts[pi + n + 1] - s->Ts[pi + n];
        const float dt_b = s->Ts[94 - pi - n] - s->Ts[95 - pi - n];  // negative
        const float dt = (rp < 8) ? dt_f : dt_b;

#pragma unroll 1
        for (int m = 0; m < 4; ++m) {
            // ---- GEMM1: H = tanh(src @ W1 + b1); 1 row-pair x 8 cols per thread ----
            ull acc[8];
            {
                ulonglong2 b0 = *(const ulonglong2*)&s->b1d[c0];
                ulonglong2 b1 = *(const ulonglong2*)&s->b1d[c0 + 2];
                ulonglong2 b2v = *(const ulonglong2*)&s->b1d[c0 + 4];
                ulonglong2 b3 = *(const ulonglong2*)&s->b1d[c0 + 6];
                acc[0] = b0.x; acc[1] = b0.y; acc[2] = b1.x; acc[3] = b1.y;
                acc[4] = b2v.x; acc[5] = b2v.y; acc[6] = b3.x; acc[7] = b3.y;
            }
#pragma unroll 8
            for (int k = 0; k < E; ++k) {
                ull y01 = *(const ull*)&s->tmpT[k][r2];
                ulonglong2 w0 = *(const ulonglong2*)&s->W1d[k][c0];
                ulonglong2 w1 = *(const ulonglong2*)&s->W1d[k][c0 + 2];
                ulonglong2 w2 = *(const ulonglong2*)&s->W1d[k][c0 + 4];
                ulonglong2 w3 = *(const ulonglong2*)&s->W1d[k][c0 + 6];
                acc[0] = fma2(w0.x, y01, acc[0]);
                acc[1] = fma2(w0.y, y01, acc[1]);
                acc[2] = fma2(w1.x, y01, acc[2]);
                acc[3] = fma2(w1.y, y01, acc[3]);
                acc[4] = fma2(w2.x, y01, acc[4]);
                acc[5] = fma2(w2.y, y01, acc[5]);
                acc[6] = fma2(w3.x, y01, acc[6]);
                acc[7] = fma2(w3.y, y01, acc[7]);
            }
#pragma unroll
            for (int ci = 0; ci < 8; ++ci) {
                float lo, hi;
                unpack2(acc[ci], lo, hi);
                *(float2*)&s->HT[c0 + ci][r2] =
                    make_float2(tanh_fast(lo), tanh_fast(hi));
            }
            __syncthreads();

            // ---- GEMM2: K = H @ W2 + b2; 1 row-pair x 4 cols per thread ----
            ull a2[4];
            {
                ulonglong2 b0 = *(const ulonglong2*)&s->b2d[c4];
                ulonglong2 b1 = *(const ulonglong2*)&s->b2d[c4 + 2];
                a2[0] = b0.x; a2[1] = b0.y; a2[2] = b1.x; a2[3] = b1.y;
            }
#pragma unroll 8
            for (int k = 0; k < EH; ++k) {
                ull h01 = *(const ull*)&s->HT[k][r2];
                ulonglong2 w0 = *(const ulonglong2*)&s->W2d[k][c4];
                ulonglong2 w1 = *(const ulonglong2*)&s->W2d[k][c4 + 2];
                a2[0] = fma2(w0.x, h01, a2[0]);
                a2[1] = fma2(w0.y, h01, a2[1]);
                a2[2] = fma2(w1.x, h01, a2[2]);
                a2[3] = fma2(w1.y, h01, a2[3]);
            }
            float kv[4][2];
#pragma unroll
            for (int c = 0; c < 4; ++c) unpack2(a2[c], kv[c][0], kv[c][1]);

            // ---- fused RK4 stage combine (P = k1-k2, Q = k1+3k2+3k3) ----
            if (m == 0) {
#pragma unroll
                for (int c = 0; c < 4; ++c) {
                    float t0, t1;
#pragma unroll
                    for (int r = 0; r < 2; ++r) {
                        Pt[c][r] = kv[c][r];
                        Qt[c][r] = kv[c][r];
                    }
                    t0 = fmaf(dt * (1.0f / 3.0f), kv[c][0], yt[c][0]);
                    t1 = fmaf(dt * (1.0f / 3.0f), kv[c][1], yt[c][1]);
                    *(float2*)&s->tmpT[c4 + c][r2] = make_float2(t0, t1);
                }
            } else if (m == 1) {
#pragma unroll
                for (int c = 0; c < 4; ++c) {
                    float t[2];
#pragma unroll
                    for (int r = 0; r < 2; ++r) {
                        // y3 = y + dt*k2 - (dt/3)*k1
                        t[r] = fmaf(dt, kv[c][r],
                                    fmaf(-dt * (1.0f / 3.0f), Pt[c][r], yt[c][r]));
                        Qt[c][r] = fmaf(3.0f, kv[c][r], Qt[c][r]);  // k1 + 3k2
                        Pt[c][r] = Pt[c][r] - kv[c][r];             // k1 - k2
                    }
                    *(float2*)&s->tmpT[c4 + c][r2] = make_float2(t[0], t[1]);
                }
            } else if (m == 2) {
#pragma unroll
                for (int c = 0; c < 4; ++c) {
                    float t[2];
#pragma unroll
                    for (int r = 0; r < 2; ++r) {
                        // y4 = y + dt*(k1 - k2 + k3)
                        t[r] = fmaf(dt, Pt[c][r] + kv[c][r], yt[c][r]);
                        Qt[c][r] = fmaf(3.0f, kv[c][r], Qt[c][r]);  // + 3k3
                    }
                    *(float2*)&s->tmpT[c4 + c][r2] = make_float2(t[0], t[1]);
                }
            } else {
#pragma unroll
                for (int c = 0; c < 4; ++c) {
#pragma unroll
                    for (int r = 0; r < 2; ++r)
                        yt[c][r] = fmaf(dt * 0.125f, Qt[c][r] + kv[c][r], yt[c][r]);
                    *(float2*)&s->tmpT[c4 + c][r2] = make_float2(yt[c][0], yt[c][1]);
                }
                // fused emission from registers
#pragma unroll
                for (int r = 0; r < 2; ++r) {
                    float4* p = (float4*)(rpt[r] + (size_t)jcur * (Hh * 64));
                    p[0] = make_float4(x0t[0][r], yt[0][r], x0t[1][r], yt[1][r]);
                    p[1] = make_float4(x0t[2][r], yt[2][r], x0t[3][r], yt[3][r]);
                }
            }
            __syncthreads();
        }
        jcur += jd;
    }
}

extern "C" void kernel_launch(void* const* d_in, const int* in_sizes, int n_in,
                              void* d_out, int out_size) {
    (void)in_sizes; (void)n_in; (void)out_size;
    cudaFuncSetAttribute(ode_kernel, cudaFuncAttributeMaxDynamicSharedMemorySize,
                         (int)sizeof(Smem));
    ode_kernel<<<384, NT, sizeof(Smem)>>>(
        (const float*)d_in[0], (const float*)d_in[1], (const float*)d_in[2],
        (const float*)d_in[3], (const float*)d_in[4], (const float*)d_in[5],
        (float2*)d_out);
}